// round 12
// baseline (speedup 1.0000x reference)
#include <cuda_runtime.h>
#include <math.h>

// QuantumPoolingLayer R12: R11 design with the smem alignment bug fixed
// (part tile declared as native float4 -> no misaligned vector access).
// Single kernel: contiguous-stream pool (256 KiB blocks) + last-block-per-batch
// sim tail overlapped with other batches' streaming. Self-resetting counters.

#define NQ 4

__device__ float2 g_part[64 * 32 * 512];   // [b][rg][m] -> (ch0, ch1) partials
__device__ int    g_cnt[64];               // per-batch arrival counter

struct c32 { float x, y; };
__device__ __forceinline__ c32 cadd(c32 a, c32 b){ return {a.x+b.x, a.y+b.y}; }
__device__ __forceinline__ c32 cmul(c32 a, c32 b){
    return { fmaf(a.x, b.x, -a.y*b.y), fmaf(a.x, b.y, a.y*b.x) };
}

// Grid 2048 (1D): bid = b*32 + rg. 512 threads, 2 blocks/SM.
// Pool phase: block streams rows [rg*2, rg*2+2), all j, all m: 256 KB CONTIGUOUS.
// Tail phase (last block of batch b): 512 sims, m = tid.
__global__ void __launch_bounds__(512, 2)
qpl_kernel(const float* __restrict__ in, const float* __restrict__ w, float* __restrict__ out)
{
    const int bid = blockIdx.x;
    const int b   = bid >> 5;
    const int rg  = bid & 31;            // 2-row group
    const int tid = threadIdx.x;
    const int ml  = tid & 127;           // m float4 lane
    const int p   = tid >> 7;            // 0..3

    __shared__ float4 spart[4][2][128];  // [p][ch][ml], 16 KB, float4-native

    // ---------------- pool phase ----------------
    {
        const float* tb = in
            + ((size_t)(b * 64 + rg * 2) * 64) * 512
            + (size_t)p * 512 + (ml << 2);

        float4 acc0 = {0.f,0.f,0.f,0.f};     // colhalf 0 (j < 32)
        float4 acc1 = {0.f,0.f,0.f,0.f};     // colhalf 1 (j >= 32)

#pragma unroll
        for (int il = 0; il < 2; il++) {
            const float* rbase = tb + (size_t)il * 64 * 512;
            {
                float4 v[8];
#pragma unroll
                for (int k = 0; k < 8; k++)
                    v[k] = __ldcs(reinterpret_cast<const float4*>(rbase + (size_t)k * 2048));
#pragma unroll
                for (int k = 0; k < 8; k++) {
                    acc0.x += v[k].x; acc0.y += v[k].y; acc0.z += v[k].z; acc0.w += v[k].w;
                }
            }
            {
                float4 v[8];
#pragma unroll
                for (int k = 0; k < 8; k++)
                    v[k] = __ldcs(reinterpret_cast<const float4*>(rbase + (size_t)(k + 8) * 2048));
#pragma unroll
                for (int k = 0; k < 8; k++) {
                    acc1.x += v[k].x; acc1.y += v[k].y; acc1.z += v[k].z; acc1.w += v[k].w;
                }
            }
        }

        spart[p][0][ml] = acc0;
        spart[p][1][ml] = acc1;
        __syncthreads();

        // tid = m: reduce over p for both col halves (scalar reads, 4B aligned OK)
        const float* pf = reinterpret_cast<const float*>(spart);
        // layout: pf[((p*2 + ch)*128 + ml4)*4 + c] = spart[p][ch][ml4].comp[c]
        // element m = ml4*4 + c  ->  index (p*2+ch)*512 + m
        float s0 = pf[0 * 512 + tid] + pf[2 * 512 + tid] + pf[4 * 512 + tid] + pf[6 * 512 + tid];
        float s1 = pf[1 * 512 + tid] + pf[3 * 512 + tid] + pf[5 * 512 + tid] + pf[7 * 512 + tid];
        g_part[(size_t)(b * 32 + rg) * 512 + tid] = make_float2(s0, s1);
    }

    // ---------------- arrival / election ----------------
    __threadfence();                     // release this thread's g_part stores
    __syncthreads();
    __shared__ int s_last;
    if (tid == 0) {
        int old = atomicAdd(&g_cnt[b], 1);
        if (old == 31) {
            __threadfence();             // acquire: partners' writes -> visible
            g_cnt[b] = 0;                // self-reset for next graph replay
            s_last = 1;
        } else {
            s_last = 0;
        }
    }
    __syncthreads();
    if (!s_last) return;

    // ---------------- sim tail: m = tid, sample n = b*512 + m ----------------
    const int m    = tid;
    const int lane = tid & 31;
    const int wrp  = tid >> 5;           // 16 warps

    // combine: 32 coalesced L2-hot float2 loads
    float quad[4] = {0.f, 0.f, 0.f, 0.f};
#pragma unroll
    for (int r = 0; r < 32; r++) {
        float2 v = __ldcg(&g_part[(size_t)(b * 32 + r) * 512 + m]);
        const int rh = r >> 4;
        quad[rh * 2 + 0] += v.x;
        quad[rh * 2 + 1] += v.y;
    }

    // warp-cooperative gate table (widx = b*8 + (m>>6), uniform per warp)
    __shared__ float sc[16][8][3][2];    // [warp][gate][comp][sin,cos]
    __shared__ float gt[16][8][4];       // [warp][gate][A,B,C,D]
    const float* wp = w + (size_t)(b * 8 + (m >> 6)) * 24;
    if (lane < 24) {
        const int g = lane / 3, c = lane - g * 3;
        float phi = wp[g * 3 + 0], th = wp[g * 3 + 1], om = wp[g * 3 + 2];
        float arg = (c == 0) ? 0.5f * th
                  : (c == 1) ? 0.5f * (phi + om)
                             : 0.5f * (phi - om);
        float sn, cs; __sincosf(arg, &sn, &cs);
        sc[wrp][g][c][0] = sn; sc[wrp][g][c][1] = cs;
    }
    __syncwarp();
    if (lane < 8) {
        float stt = sc[wrp][lane][0][0], ctt = sc[wrp][lane][0][1];
        float sa  = sc[wrp][lane][1][0], ca  = sc[wrp][lane][1][1];
        float sb  = sc[wrp][lane][2][0], cb  = sc[wrp][lane][2][1];
        gt[wrp][lane][0] = ctt * ca;   // A
        gt[wrp][lane][1] = ctt * sa;   // B
        gt[wrp][lane][2] = stt * cb;   // C
        gt[wrp][lane][3] = stt * sb;   // D
    }
    __syncwarp();

    float x[4];
#pragma unroll
    for (int q = 0; q < 4; q++)
        x[q] = tanhf(quad[q] * (1.0f / 1024.0f));

    // circuit
    c32 s[16];
#pragma unroll
    for (int k = 0; k < 16; k++) s[k] = {0.f, 0.f};
    s[0].x = 1.f;

#pragma unroll
    for (int q = 0; q < NQ; q++) {       // RY(x*pi); mask = 8>>q
        float half = x[q] * 1.57079632679489662f;
        float sn, cs; __sincosf(half, &sn, &cs);
        const int mk = 8 >> q;
#pragma unroll
        for (int k = 0; k < 16; k++) {
            if (!(k & mk)) {
                c32 v0 = s[k], v1 = s[k | mk];
                s[k]      = { cs*v0.x - sn*v1.x, cs*v0.y - sn*v1.y };
                s[k | mk] = { sn*v0.x + cs*v1.x, sn*v0.y + cs*v1.y };
            }
        }
    }

#pragma unroll
    for (int layer = 0; layer < 2; layer++) {
#pragma unroll
        for (int q = 0; q < NQ; q++) {
            const float* G = gt[wrp][layer * 4 + q];
            const float A = G[0], B = G[1], C = G[2], D = G[3];
            c32 U00 = {  A, -B };
            c32 U01 = { -C, -D };
            c32 U10 = {  C, -D };
            c32 U11 = {  A,  B };
            const int mk = 8 >> q;
#pragma unroll
            for (int k = 0; k < 16; k++) {
                if (!(k & mk)) {
                    c32 v0 = s[k], v1 = s[k | mk];
                    c32 n0 = cadd(cmul(U00, v0), cmul(U01, v1));
                    c32 n1 = cadd(cmul(U10, v0), cmul(U11, v1));
                    s[k] = n0; s[k | mk] = n1;
                }
            }
        }
#pragma unroll
        for (int c = 0; c < NQ; c++) {   // CNOT cascade: amplitude swaps
#pragma unroll
            for (int t = c + 1; t < NQ; t++) {
                const int cm = 8 >> c, tm = 8 >> t;
#pragma unroll
                for (int k = 0; k < 16; k++) {
                    if ((k & cm) && !(k & tm)) {
                        c32 tmp = s[k]; s[k] = s[k | tm]; s[k | tm] = tmp;
                    }
                }
            }
        }
    }

    float pr = 0.f;
#pragma unroll
    for (int k = 0; k < 16; k++) {
        float t2 = fmaf(s[k].x, s[k].x, s[k].y * s[k].y);
        pr += (k < 8) ? t2 : -t2;
    }
    out[b * 512 + m] = pr;
}

extern "C" void kernel_launch(void* const* d_in, const int* in_sizes, int n_in,
                              void* d_out, int out_size)
{
    const float* in = (const float*)d_in[0];
    const float* w  = (const float*)d_in[1];
    if (n_in >= 2 && in_sizes[0] < in_sizes[1]) {   // defensive: identify by size
        in = (const float*)d_in[1];
        w  = (const float*)d_in[0];
    }
    qpl_kernel<<<2048, 512>>>(in, w, (float*)d_out);
}

// round 13
// speedup vs baseline: 1.0729x; 1.0729x over previous
#include <cuda_runtime.h>
#include <cuda_fp16.h>
#include <math.h>

// QuantumPoolingLayer R13: two-kernel split (fusion is confirmed-poison).
//  K1: contiguous-stream pool (256 KiB blocks, ~94% HBM), partials -> half2 (4 MB).
//  K2: 256-thread blocks; 4 loader threads/sample (4096 warps for the scratch
//      read), smem reduce, then 1 thread/sample sim with block-uniform gate table.

#define NQ 4

__device__ half2 g_part[64 * 32 * 512];   // [b][rg][m] -> (ch0, ch1) partials, 4 MB

struct c32 { float x, y; };
__device__ __forceinline__ c32 cadd(c32 a, c32 b){ return {a.x+b.x, a.y+b.y}; }
__device__ __forceinline__ c32 cmul(c32 a, c32 b){
    return { fmaf(a.x, b.x, -a.y*b.y), fmaf(a.x, b.y, a.y*b.x) };
}
__device__ __forceinline__ float fast_tanh(float x) {
    float e = __expf(2.0f * x);
    return __fdividef(e - 1.0f, e + 1.0f);
}

// K1: grid (rg=32, b=64), 512 threads, 2 blocks/SM.
// Block streams rows [rg*2, rg*2+2), all j, all m: 256 KB CONTIGUOUS.
__global__ void __launch_bounds__(512, 2)
pool_kernel(const float* __restrict__ in)
{
    const int rg = blockIdx.x;           // 2-row group, 0..31
    const int b  = blockIdx.y;
    const int tid = threadIdx.x;
    const int ml  = tid & 127;           // m float4 lane
    const int p   = tid >> 7;            // 0..3

    const float* tb = in
        + ((size_t)(b * 64 + rg * 2) * 64) * 512
        + (size_t)p * 512 + (ml << 2);

    float4 acc0 = {0.f,0.f,0.f,0.f};     // colhalf 0 (j < 32)
    float4 acc1 = {0.f,0.f,0.f,0.f};     // colhalf 1 (j >= 32)

#pragma unroll
    for (int il = 0; il < 2; il++) {
        const float* rbase = tb + (size_t)il * 64 * 512;
        {
            float4 v[8];
#pragma unroll
            for (int k = 0; k < 8; k++)
                v[k] = __ldcs(reinterpret_cast<const float4*>(rbase + (size_t)k * 2048));
#pragma unroll
            for (int k = 0; k < 8; k++) {
                acc0.x += v[k].x; acc0.y += v[k].y; acc0.z += v[k].z; acc0.w += v[k].w;
            }
        }
        {
            float4 v[8];
#pragma unroll
            for (int k = 0; k < 8; k++)
                v[k] = __ldcs(reinterpret_cast<const float4*>(rbase + (size_t)(k + 8) * 2048));
#pragma unroll
            for (int k = 0; k < 8; k++) {
                acc1.x += v[k].x; acc1.y += v[k].y; acc1.z += v[k].z; acc1.w += v[k].w;
            }
        }
    }

    __shared__ __align__(16) float part[4][2][512];    // [p][ch][m], 16 KB
    reinterpret_cast<float4*>(part[p][0])[ml] = acc0;
    reinterpret_cast<float4*>(part[p][1])[ml] = acc1;
    __syncthreads();

    {
        float s0 = part[0][0][tid] + part[1][0][tid] + part[2][0][tid] + part[3][0][tid];
        float s1 = part[0][1][tid] + part[1][1][tid] + part[2][1][tid] + part[3][1][tid];
        g_part[(size_t)(b * 32 + rg) * 512 + tid] = __floats2half2_rn(s0, s1);
    }
}

// K2: grid 512, 256 threads. Block handles samples [blockIdx*64, +64);
// widx = n>>6 == blockIdx (uniform). Loader t = tid>>6 loads rgs [8t, 8t+8).
__global__ void __launch_bounds__(256)
sim_kernel(const float* __restrict__ w, float* __restrict__ out)
{
    const int tid = threadIdx.x;
    const int s   = tid & 63;            // sample slot in block
    const int t   = tid >> 6;            // loader index 0..3
    const int n   = blockIdx.x * 64 + s;
    const int b   = n >> 9;
    const int m   = n & 511;

    // --- parallel scratch read: 8 coalesced half2 loads per thread ---
    float q[4] = {0.f, 0.f, 0.f, 0.f};
#pragma unroll
    for (int i = 0; i < 8; i++) {
        const int rg = t * 8 + i;
        float2 v = __half22float2(g_part[(size_t)(b * 32 + rg) * 512 + m]);
        const int rh = rg >> 4;
        q[rh * 2 + 0] += v.x;
        q[rh * 2 + 1] += v.y;
    }

    __shared__ float sq[4][4][64];       // [t][quad][s], 4 KB
#pragma unroll
    for (int qd = 0; qd < 4; qd++) sq[t][qd][s] = q[qd];

    // --- block-uniform gate table (widx == blockIdx) ---
    __shared__ float sc[8][3][2];        // [gate][comp][sin,cos]
    __shared__ float gt[8][4];           // [gate][A,B,C,D]
    const float* wp = w + (size_t)blockIdx.x * 24;
    if (tid >= 64 && tid < 88) {         // loader group 1 builds the table
        const int l = tid - 64;
        const int g = l / 3, c = l - g * 3;
        float phi = wp[g * 3 + 0], th = wp[g * 3 + 1], om = wp[g * 3 + 2];
        float arg = (c == 0) ? 0.5f * th
                  : (c == 1) ? 0.5f * (phi + om)
                             : 0.5f * (phi - om);
        float sn, cs; __sincosf(arg, &sn, &cs);
        sc[g][c][0] = sn; sc[g][c][1] = cs;
    }
    __syncthreads();
    if (tid >= 64 && tid < 72) {
        const int g = tid - 64;
        float stt = sc[g][0][0], ctt = sc[g][0][1];
        float sa  = sc[g][1][0], ca  = sc[g][1][1];
        float sb  = sc[g][2][0], cb  = sc[g][2][1];
        gt[g][0] = ctt * ca;   // A
        gt[g][1] = ctt * sa;   // B
        gt[g][2] = stt * cb;   // C
        gt[g][3] = stt * sb;   // D
    }
    __syncthreads();

    if (tid >= 64) return;

    // --- per-sample sim (tid = s, 2 warps/block) ---
    float x[4];
#pragma unroll
    for (int qd = 0; qd < 4; qd++) {
        float quad = sq[0][qd][tid] + sq[1][qd][tid] + sq[2][qd][tid] + sq[3][qd][tid];
        x[qd] = fast_tanh(quad * (1.0f / 1024.0f));
    }

    c32 st[16];
#pragma unroll
    for (int k = 0; k < 16; k++) st[k] = {0.f, 0.f};
    st[0].x = 1.f;

#pragma unroll
    for (int q2 = 0; q2 < NQ; q2++) {    // RY(x*pi); mask = 8>>q
        float half = x[q2] * 1.57079632679489662f;
        float sn, cs; __sincosf(half, &sn, &cs);
        const int mk = 8 >> q2;
#pragma unroll
        for (int k = 0; k < 16; k++) {
            if (!(k & mk)) {
                c32 v0 = st[k], v1 = st[k | mk];
                st[k]      = { cs*v0.x - sn*v1.x, cs*v0.y - sn*v1.y };
                st[k | mk] = { sn*v0.x + cs*v1.x, sn*v0.y + cs*v1.y };
            }
        }
    }

#pragma unroll
    for (int layer = 0; layer < 2; layer++) {
#pragma unroll
        for (int q2 = 0; q2 < NQ; q2++) {
            const float* G = gt[layer * 4 + q2];
            const float A = G[0], B = G[1], C = G[2], D = G[3];
            c32 U00 = {  A, -B };
            c32 U01 = { -C, -D };
            c32 U10 = {  C, -D };
            c32 U11 = {  A,  B };
            const int mk = 8 >> q2;
#pragma unroll
            for (int k = 0; k < 16; k++) {
                if (!(k & mk)) {
                    c32 v0 = st[k], v1 = st[k | mk];
                    c32 n0 = cadd(cmul(U00, v0), cmul(U01, v1));
                    c32 n1 = cadd(cmul(U10, v0), cmul(U11, v1));
                    st[k] = n0; st[k | mk] = n1;
                }
            }
        }
#pragma unroll
        for (int c = 0; c < NQ; c++) {   // CNOT cascade: amplitude swaps
#pragma unroll
            for (int t2 = c + 1; t2 < NQ; t2++) {
                const int cm = 8 >> c, tm = 8 >> t2;
#pragma unroll
                for (int k = 0; k < 16; k++) {
                    if ((k & cm) && !(k & tm)) {
                        c32 tmp = st[k]; st[k] = st[k | tm]; st[k | tm] = tmp;
                    }
                }
            }
        }
    }

    float pr = 0.f;
#pragma unroll
    for (int k = 0; k < 16; k++) {
        float t2 = fmaf(st[k].x, st[k].x, st[k].y * st[k].y);
        pr += (k < 8) ? t2 : -t2;
    }
    out[n] = pr;
}

extern "C" void kernel_launch(void* const* d_in, const int* in_sizes, int n_in,
                              void* d_out, int out_size)
{
    const float* in = (const float*)d_in[0];
    const float* w  = (const float*)d_in[1];
    if (n_in >= 2 && in_sizes[0] < in_sizes[1]) {   // defensive: identify by size
        in = (const float*)d_in[1];
        w  = (const float*)d_in[0];
    }
    dim3 grid1(32, 64);
    pool_kernel<<<grid1, 512>>>(in);
    sim_kernel<<<512, 256>>>(w, (float*)d_out);
}

// round 14
// speedup vs baseline: 1.0807x; 1.0072x over previous
#include <cuda_runtime.h>
#include <math.h>

// QuantumPoolingLayer R14: R9 base (contiguous pool + fp32 float2 scratch +
// 512x64 sim) with the sim circuit cut algebraically: layer-1 state is a
// tensor product of 4 single-qubit states (built in ~130 instr instead of
// ~800 butterfly instr). CNOT cascades are free register permutations.

#define NQ 4

__device__ float2 g_part[64 * 32 * 512];   // [b][rg][m] -> (ch0, ch1) partials

struct c32 { float x, y; };
__device__ __forceinline__ c32 cadd(c32 a, c32 b){ return {a.x+b.x, a.y+b.y}; }
__device__ __forceinline__ c32 cmul(c32 a, c32 b){
    return { fmaf(a.x, b.x, -a.y*b.y), fmaf(a.x, b.y, a.y*b.x) };
}

// K1: grid (rg=32, b=64), 512 threads, 2 blocks/SM.
// Block streams rows [rg*2, rg*2+2), all j, all m: 256 KB CONTIGUOUS.
__global__ void __launch_bounds__(512, 2)
pool_kernel(const float* __restrict__ in)
{
    const int rg = blockIdx.x;           // 2-row group, 0..31
    const int b  = blockIdx.y;
    const int tid = threadIdx.x;
    const int ml  = tid & 127;           // m float4 lane
    const int p   = tid >> 7;            // 0..3

    const float* tb = in
        + ((size_t)(b * 64 + rg * 2) * 64) * 512
        + (size_t)p * 512 + (ml << 2);

    float4 acc0 = {0.f,0.f,0.f,0.f};     // colhalf 0 (j < 32)
    float4 acc1 = {0.f,0.f,0.f,0.f};     // colhalf 1 (j >= 32)

#pragma unroll
    for (int il = 0; il < 2; il++) {
        const float* rbase = tb + (size_t)il * 64 * 512;
        {
            float4 v[8];
#pragma unroll
            for (int k = 0; k < 8; k++)
                v[k] = __ldcs(reinterpret_cast<const float4*>(rbase + (size_t)k * 2048));
#pragma unroll
            for (int k = 0; k < 8; k++) {
                acc0.x += v[k].x; acc0.y += v[k].y; acc0.z += v[k].z; acc0.w += v[k].w;
            }
        }
        {
            float4 v[8];
#pragma unroll
            for (int k = 0; k < 8; k++)
                v[k] = __ldcs(reinterpret_cast<const float4*>(rbase + (size_t)(k + 8) * 2048));
#pragma unroll
            for (int k = 0; k < 8; k++) {
                acc1.x += v[k].x; acc1.y += v[k].y; acc1.z += v[k].z; acc1.w += v[k].w;
            }
        }
    }

    __shared__ __align__(16) float part[4][2][512];    // [p][ch][m], 16 KB
    reinterpret_cast<float4*>(part[p][0])[ml] = acc0;
    reinterpret_cast<float4*>(part[p][1])[ml] = acc1;
    __syncthreads();

    {
        float s0 = part[0][0][tid] + part[1][0][tid] + part[2][0][tid] + part[3][0][tid];
        float s1 = part[0][1][tid] + part[1][1][tid] + part[2][1][tid] + part[3][1][tid];
        g_part[(size_t)(b * 32 + rg) * 512 + tid] = make_float2(s0, s1);
    }
}

// K2: one thread per sample, 512 blocks x 64 threads. Warp shares widx.
__global__ void __launch_bounds__(64)
sim_kernel(const float* __restrict__ w, float* __restrict__ out)
{
    const int n    = blockIdx.x * 64 + threadIdx.x;  // sample = b*512 + m
    const int lane = threadIdx.x & 31;
    const int wrp  = threadIdx.x >> 5;
    const int b = n >> 9;
    const int m = n & 511;

    // --- scratch combine: 32 coalesced float2 loads, independent ---
    float quad[4] = {0.f, 0.f, 0.f, 0.f};
#pragma unroll
    for (int rg = 0; rg < 32; rg++) {
        float2 v = g_part[(size_t)(b * 32 + rg) * 512 + m];
        const int rh = rg >> 4;
        quad[rh * 2 + 0] += v.x;
        quad[rh * 2 + 1] += v.y;
    }

    // --- warp-cooperative gate table (widx = n>>6 uniform across warp) ---
    __shared__ float sc[2][8][3][2];     // [warp][gate][comp][sin,cos]
    __shared__ float gt[2][8][4];        // [warp][gate][A,B,C,D]
    const float* wp = w + (size_t)(n >> 6) * 24;
    if (lane < 24) {
        const int g = lane / 3, c = lane - g * 3;
        float phi = wp[g * 3 + 0], th = wp[g * 3 + 1], om = wp[g * 3 + 2];
        float arg = (c == 0) ? 0.5f * th
                  : (c == 1) ? 0.5f * (phi + om)
                             : 0.5f * (phi - om);
        float sn, cs; __sincosf(arg, &sn, &cs);
        sc[wrp][g][c][0] = sn; sc[wrp][g][c][1] = cs;
    }
    __syncwarp();
    if (lane < 8) {
        float stt = sc[wrp][lane][0][0], ctt = sc[wrp][lane][0][1];
        float sa  = sc[wrp][lane][1][0], ca  = sc[wrp][lane][1][1];
        float sb  = sc[wrp][lane][2][0], cb  = sc[wrp][lane][2][1];
        gt[wrp][lane][0] = ctt * ca;   // A
        gt[wrp][lane][1] = ctt * sa;   // B
        gt[wrp][lane][2] = stt * cb;   // C
        gt[wrp][lane][3] = stt * sb;   // D
    }
    __syncwarp();

    // --- per-qubit 2-vectors: RY(x*pi)|0> then layer-1 Rot (product state) ---
    // RY|0> = [cos(x*pi/2), sin(x*pi/2)] (real). Rot U: u0 = U00*c + U01*s,
    // u1 = U10*c + U11*s with U00=(A,-B), U01=(-C,-D), U10=(C,-D), U11=(A,B).
    c32 qv0[NQ], qv1[NQ];
#pragma unroll
    for (int q = 0; q < NQ; q++) {
        float x = tanhf(quad[q] * (1.0f / 1024.0f));
        float sn, cs; __sincosf(x * 1.57079632679489662f, &sn, &cs);
        const float A = gt[wrp][q][0], B = gt[wrp][q][1];
        const float C = gt[wrp][q][2], D = gt[wrp][q][3];
        qv0[q] = { fmaf(A, cs, -C * sn), fmaf(-B, cs, -D * sn) };
        qv1[q] = { fmaf(C, cs,  A * sn), fmaf(-D, cs,  B * sn) };
    }

    // --- tensor product -> 16 amplitudes (wire 0 = MSB = bit 3) ---
    c32 p01[4], p23[4];
#pragma unroll
    for (int i = 0; i < 2; i++)
#pragma unroll
        for (int j = 0; j < 2; j++) {
            p01[i * 2 + j] = cmul(i ? qv1[0] : qv0[0], j ? qv1[1] : qv0[1]);
            p23[i * 2 + j] = cmul(i ? qv1[2] : qv0[2], j ? qv1[3] : qv0[3]);
        }
    c32 s[16];
#pragma unroll
    for (int k = 0; k < 16; k++)
        s[k] = cmul(p01[k >> 2], p23[k & 3]);

    // --- CNOT cascade #1 (register permutation, free) ---
#pragma unroll
    for (int c = 0; c < NQ; c++)
#pragma unroll
        for (int t = c + 1; t < NQ; t++) {
            const int cm = 8 >> c, tm = 8 >> t;
#pragma unroll
            for (int k = 0; k < 16; k++)
                if ((k & cm) && !(k & tm)) {
                    c32 tmp = s[k]; s[k] = s[k | tm]; s[k | tm] = tmp;
                }
        }

    // --- layer-2 Rot gates (full butterflies) ---
#pragma unroll
    for (int q = 0; q < NQ; q++) {
        const float* G = gt[wrp][4 + q];
        const float A = G[0], B = G[1], C = G[2], D = G[3];
        c32 U00 = {  A, -B };
        c32 U01 = { -C, -D };
        c32 U10 = {  C, -D };
        c32 U11 = {  A,  B };
        const int mk = 8 >> q;
#pragma unroll
        for (int k = 0; k < 16; k++) {
            if (!(k & mk)) {
                c32 v0 = s[k], v1 = s[k | mk];
                c32 n0 = cadd(cmul(U00, v0), cmul(U01, v1));
                c32 n1 = cadd(cmul(U10, v0), cmul(U11, v1));
                s[k] = n0; s[k | mk] = n1;
            }
        }
    }

    // --- CNOT cascade #2 (free) ---
#pragma unroll
    for (int c = 0; c < NQ; c++)
#pragma unroll
        for (int t = c + 1; t < NQ; t++) {
            const int cm = 8 >> c, tm = 8 >> t;
#pragma unroll
            for (int k = 0; k < 16; k++)
                if ((k & cm) && !(k & tm)) {
                    c32 tmp = s[k]; s[k] = s[k | tm]; s[k | tm] = tmp;
                }
        }

    // --- <Z0> ---
    float pr = 0.f;
#pragma unroll
    for (int k = 0; k < 16; k++) {
        float t2 = fmaf(s[k].x, s[k].x, s[k].y * s[k].y);
        pr += (k < 8) ? t2 : -t2;
    }
    out[n] = pr;
}

extern "C" void kernel_launch(void* const* d_in, const int* in_sizes, int n_in,
                              void* d_out, int out_size)
{
    const float* in = (const float*)d_in[0];
    const float* w  = (const float*)d_in[1];
    if (n_in >= 2 && in_sizes[0] < in_sizes[1]) {   // defensive: identify by size
        in = (const float*)d_in[1];
        w  = (const float*)d_in[0];
    }
    dim3 grid1(32, 64);
    pool_kernel<<<grid1, 512>>>(in);
    sim_kernel<<<512, 64>>>(w, (float*)d_out);
}

// round 15
// speedup vs baseline: 1.1310x; 1.0466x over previous
#include <cuda_runtime.h>
#include <cuda_fp16.h>
#include <math.h>

// QuantumPoolingLayer R15: R14 base with (1) half2 scratch (4.2 MB, halves the
// sim's DRAM read — partials were L2-evicted by the 512 MB stream) and
// (2) CNOT cascade #2 deleted (bit3 is never a target -> <Z0> invariant).

#define NQ 4

__device__ half2 g_part[64 * 32 * 512];   // [b][rg][m] -> (ch0, ch1) partials

struct c32 { float x, y; };
__device__ __forceinline__ c32 cadd(c32 a, c32 b){ return {a.x+b.x, a.y+b.y}; }
__device__ __forceinline__ c32 cmul(c32 a, c32 b){
    return { fmaf(a.x, b.x, -a.y*b.y), fmaf(a.x, b.y, a.y*b.x) };
}

// K1: grid (rg=32, b=64), 512 threads, 2 blocks/SM.
// Block streams rows [rg*2, rg*2+2), all j, all m: 256 KB CONTIGUOUS.
__global__ void __launch_bounds__(512, 2)
pool_kernel(const float* __restrict__ in)
{
    const int rg = blockIdx.x;           // 2-row group, 0..31
    const int b  = blockIdx.y;
    const int tid = threadIdx.x;
    const int ml  = tid & 127;           // m float4 lane
    const int p   = tid >> 7;            // 0..3

    const float* tb = in
        + ((size_t)(b * 64 + rg * 2) * 64) * 512
        + (size_t)p * 512 + (ml << 2);

    float4 acc0 = {0.f,0.f,0.f,0.f};     // colhalf 0 (j < 32)
    float4 acc1 = {0.f,0.f,0.f,0.f};     // colhalf 1 (j >= 32)

#pragma unroll
    for (int il = 0; il < 2; il++) {
        const float* rbase = tb + (size_t)il * 64 * 512;
        {
            float4 v[8];
#pragma unroll
            for (int k = 0; k < 8; k++)
                v[k] = __ldcs(reinterpret_cast<const float4*>(rbase + (size_t)k * 2048));
#pragma unroll
            for (int k = 0; k < 8; k++) {
                acc0.x += v[k].x; acc0.y += v[k].y; acc0.z += v[k].z; acc0.w += v[k].w;
            }
        }
        {
            float4 v[8];
#pragma unroll
            for (int k = 0; k < 8; k++)
                v[k] = __ldcs(reinterpret_cast<const float4*>(rbase + (size_t)(k + 8) * 2048));
#pragma unroll
            for (int k = 0; k < 8; k++) {
                acc1.x += v[k].x; acc1.y += v[k].y; acc1.z += v[k].z; acc1.w += v[k].w;
            }
        }
    }

    __shared__ __align__(16) float part[4][2][512];    // [p][ch][m], 16 KB
    reinterpret_cast<float4*>(part[p][0])[ml] = acc0;
    reinterpret_cast<float4*>(part[p][1])[ml] = acc1;
    __syncthreads();

    {
        float s0 = part[0][0][tid] + part[1][0][tid] + part[2][0][tid] + part[3][0][tid];
        float s1 = part[0][1][tid] + part[1][1][tid] + part[2][1][tid] + part[3][1][tid];
        g_part[(size_t)(b * 32 + rg) * 512 + tid] = __floats2half2_rn(s0, s1);
    }
}

// K2: one thread per sample, 512 blocks x 64 threads. Warp shares widx.
__global__ void __launch_bounds__(64)
sim_kernel(const float* __restrict__ w, float* __restrict__ out)
{
    const int n    = blockIdx.x * 64 + threadIdx.x;  // sample = b*512 + m
    const int lane = threadIdx.x & 31;
    const int wrp  = threadIdx.x >> 5;
    const int b = n >> 9;
    const int m = n & 511;

    // --- scratch combine: 32 coalesced half2 loads, independent ---
    float quad[4] = {0.f, 0.f, 0.f, 0.f};
#pragma unroll
    for (int rg = 0; rg < 32; rg++) {
        float2 v = __half22float2(g_part[(size_t)(b * 32 + rg) * 512 + m]);
        const int rh = rg >> 4;
        quad[rh * 2 + 0] += v.x;
        quad[rh * 2 + 1] += v.y;
    }

    // --- warp-cooperative gate table (widx = n>>6 uniform across warp) ---
    __shared__ float sc[2][8][3][2];     // [warp][gate][comp][sin,cos]
    __shared__ float gt[2][8][4];        // [warp][gate][A,B,C,D]
    const float* wp = w + (size_t)(n >> 6) * 24;
    if (lane < 24) {
        const int g = lane / 3, c = lane - g * 3;
        float phi = wp[g * 3 + 0], th = wp[g * 3 + 1], om = wp[g * 3 + 2];
        float arg = (c == 0) ? 0.5f * th
                  : (c == 1) ? 0.5f * (phi + om)
                             : 0.5f * (phi - om);
        float sn, cs; __sincosf(arg, &sn, &cs);
        sc[wrp][g][c][0] = sn; sc[wrp][g][c][1] = cs;
    }
    __syncwarp();
    if (lane < 8) {
        float stt = sc[wrp][lane][0][0], ctt = sc[wrp][lane][0][1];
        float sa  = sc[wrp][lane][1][0], ca  = sc[wrp][lane][1][1];
        float sb  = sc[wrp][lane][2][0], cb  = sc[wrp][lane][2][1];
        gt[wrp][lane][0] = ctt * ca;   // A
        gt[wrp][lane][1] = ctt * sa;   // B
        gt[wrp][lane][2] = stt * cb;   // C
        gt[wrp][lane][3] = stt * sb;   // D
    }
    __syncwarp();

    // --- per-qubit 2-vectors: RY(x*pi)|0> then layer-1 Rot (product state) ---
    c32 qv0[NQ], qv1[NQ];
#pragma unroll
    for (int q = 0; q < NQ; q++) {
        float x = tanhf(quad[q] * (1.0f / 1024.0f));
        float sn, cs; __sincosf(x * 1.57079632679489662f, &sn, &cs);
        const float A = gt[wrp][q][0], B = gt[wrp][q][1];
        const float C = gt[wrp][q][2], D = gt[wrp][q][3];
        qv0[q] = { fmaf(A, cs, -C * sn), fmaf(-B, cs, -D * sn) };
        qv1[q] = { fmaf(C, cs,  A * sn), fmaf(-D, cs,  B * sn) };
    }

    // --- tensor product -> 16 amplitudes (wire 0 = MSB = bit 3) ---
    c32 p01[4], p23[4];
#pragma unroll
    for (int i = 0; i < 2; i++)
#pragma unroll
        for (int j = 0; j < 2; j++) {
            p01[i * 2 + j] = cmul(i ? qv1[0] : qv0[0], j ? qv1[1] : qv0[1]);
            p23[i * 2 + j] = cmul(i ? qv1[2] : qv0[2], j ? qv1[3] : qv0[3]);
        }
    c32 s[16];
#pragma unroll
    for (int k = 0; k < 16; k++)
        s[k] = cmul(p01[k >> 2], p23[k & 3]);

    // --- CNOT cascade #1 (register permutation) ---
#pragma unroll
    for (int c = 0; c < NQ; c++)
#pragma unroll
        for (int t = c + 1; t < NQ; t++) {
            const int cm = 8 >> c, tm = 8 >> t;
#pragma unroll
            for (int k = 0; k < 16; k++)
                if ((k & cm) && !(k & tm)) {
                    c32 tmp = s[k]; s[k] = s[k | tm]; s[k | tm] = tmp;
                }
        }

    // --- layer-2 Rot gates (full butterflies) ---
#pragma unroll
    for (int q = 0; q < NQ; q++) {
        const float* G = gt[wrp][4 + q];
        const float A = G[0], B = G[1], C = G[2], D = G[3];
        c32 U00 = {  A, -B };
        c32 U01 = { -C, -D };
        c32 U10 = {  C, -D };
        c32 U11 = {  A,  B };
        const int mk = 8 >> q;
#pragma unroll
        for (int k = 0; k < 16; k++) {
            if (!(k & mk)) {
                c32 v0 = s[k], v1 = s[k | mk];
                c32 n0 = cadd(cmul(U00, v0), cmul(U01, v1));
                c32 n1 = cadd(cmul(U10, v0), cmul(U11, v1));
                s[k] = n0; s[k | mk] = n1;
            }
        }
    }

    // --- CNOT cascade #2: bit 3 (wire 0) is never a target -> <Z0> invariant.
    //     Skipped entirely; sign determined by pre-cascade bit 3. ---
    float pr = 0.f;
#pragma unroll
    for (int k = 0; k < 16; k++) {
        float t2 = fmaf(s[k].x, s[k].x, s[k].y * s[k].y);
        pr += (k < 8) ? t2 : -t2;
    }
    out[n] = pr;
}

extern "C" void kernel_launch(void* const* d_in, const int* in_sizes, int n_in,
                              void* d_out, int out_size)
{
    const float* in = (const float*)d_in[0];
    const float* w  = (const float*)d_in[1];
    if (n_in >= 2 && in_sizes[0] < in_sizes[1]) {   // defensive: identify by size
        in = (const float*)d_in[1];
        w  = (const float*)d_in[0];
    }
    dim3 grid1(32, 64);
    pool_kernel<<<grid1, 512>>>(in);
    sim_kernel<<<512, 64>>>(w, (float*)d_out);
}